// round 15
// baseline (speedup 1.0000x reference)
#include <cuda_runtime.h>
#include <cstdint>
#include <math.h>

#define N_PRIORS 268800
#define NF4 (N_PRIORS / 4)      // 67200 float4 score packets
#define MAXK 750
#define CAP 2048                // candidate slot capacity (score > CTHR)
#define CTHR 0.9966f            // E[ncand] ~ 914
#define SUPK 32                 // max recorded suppressors per candidate
#define AMB_MAX 64              // max ambiguous candidates on fast path
#define NSUPW ((N_PRIORS + 31) / 32)
#define FULLM 0xffffffffu
#define NB 66                   // persistent blocks (< 148 SMs -> all co-resident)

// ---------------- static device scratch (zero-init; reset at tail) --------------
__device__ float4 g_boxes[N_PRIORS];            // FALLBACK-ONLY scratch
__device__ unsigned long long g_ckeys[CAP];
__device__ float4 g_cbox[CAP];
__device__ float  g_carea[CAP];
__device__ int    g_cnt;
__device__ int    g_rank[CAP];
__device__ int    g_slotofrank[CAP];
__device__ int    g_supcnt[CAP];
__device__ int    g_suplist[CAP * SUPK];
__device__ unsigned int g_supp[NSUPW];
__device__ int    g_barA, g_barB;               // grid barrier counters

// ---------------- priors, pure f32 (bit-identical to numpy f64->f32 path) -------
__device__ __forceinline__ void get_prior(int i, float& px, float& py, float& ps) {
    int r, f; float D, ps0, ps1;
    if (i < 204800)      { r = i;          f = 320; D = 640.0f;
                           ps0 = (float)(16.0  / 2560.0); ps1 = (float)(32.0  / 2560.0); }
    else if (i < 256000) { r = i - 204800; f = 160; D = 320.0f;
                           ps0 = (float)(64.0  / 2560.0); ps1 = (float)(128.0 / 2560.0); }
    else                 { r = i - 256000; f = 80;  D = 160.0f;
                           ps0 = (float)(256.0 / 2560.0); ps1 = (float)(512.0 / 2560.0); }
    int c = r >> 1;
    int x = c % f;
    int y = c / f;
    px = (float)(2 * x + 1) / D;
    py = (float)(2 * y + 1) / D;
    ps = (r & 1) ? ps1 : ps0;
}

__device__ __forceinline__ float4 decode_box(const float4 l, float px, float py, float ps) {
    float cx = __fadd_rn(px, __fmul_rn(__fmul_rn(l.x, 0.1f), ps));
    float cy = __fadd_rn(py, __fmul_rn(__fmul_rn(l.y, 0.1f), ps));
    float w = __fmul_rn(ps, expf(__fmul_rn(l.z, 0.2f)));
    float h = __fmul_rn(ps, expf(__fmul_rn(l.w, 0.2f)));
    float x1 = __fmul_rn(__fsub_rn(cx, __fmul_rn(w, 0.5f)), 2560.0f);
    float y1 = __fmul_rn(__fsub_rn(cy, __fmul_rn(h, 0.5f)), 2560.0f);
    float x2 = __fmul_rn(__fadd_rn(cx, __fmul_rn(w, 0.5f)), 2560.0f);
    float y2 = __fmul_rn(__fadd_rn(cy, __fmul_rn(h, 0.5f)), 2560.0f);
    return make_float4(x1, y1, x2, y2);
}

__device__ __forceinline__ float box_area(const float4 b) {
    return __fmul_rn(__fadd_rn(__fsub_rn(b.z, b.x), 1.0f),
                     __fadd_rn(__fsub_rn(b.w, b.y), 1.0f));
}

// IoU > 0.4 with +1 convention; FP-symmetric in operand order.
__device__ __forceinline__ bool iou_gt(const float4 bi, const float ai,
                                       const float4 bj, const float aj) {
    float xx1 = fmaxf(bi.x, bj.x);
    float yy1 = fmaxf(bi.y, bj.y);
    float xx2 = fminf(bi.z, bj.z);
    float yy2 = fminf(bi.w, bj.w);
    float iw = fmaxf(0.0f, __fadd_rn(__fsub_rn(xx2, xx1), 1.0f));
    float ih = fmaxf(0.0f, __fadd_rn(__fsub_rn(yy2, yy1), 1.0f));
    float inter = __fmul_rn(iw, ih);
    float uni = __fsub_rn(__fadd_rn(ai, aj), inter);
    return (inter / uni) > 0.4f;       // IEEE divide, like reference
}

// ---------------- shared memory (rank buffer unioned with resolve state) --------
struct RV {
    unsigned char s_kept[CAP];
    int s_cnt[CAP];
    unsigned int s_kb[64], s_ab[64];
    int s_wbase[64], s_awbase[64];
    int s_alist[AMB_MAX], s_alist2[AMB_MAX], s_arank[AMB_MAX];
    int s_asup[AMB_MAX * 32];
    int s_keep_orig[MAXK];
    int s_namb, s_ktot, s_fkept;
    float rs_[1024];
    int   ri_[1024];
};
union SmemU {
    unsigned long long sk[CAP];     // rank phase
    RV rv;                          // resolve phase (block 0, later)
};

// ================= ONE persistent kernel: decode | rank+suppress | resolve ======
__global__ void __launch_bounds__(1024, 1)
fused_kernel(const float* __restrict__ loc,
             const float* __restrict__ scores,
             const float* __restrict__ landms,
             const float* __restrict__ thrp,
             float* __restrict__ out) {
    __shared__ SmemU smu;
    int tid = threadIdx.x;
    int bid = blockIdx.x;
    int lane = tid & 31;
    int wi = tid >> 5;
    unsigned lt = (1u << lane) - 1u;

    // ---------------- phase 1: decode (candidates only, float4 scores) ----------
    {
        int f4 = bid * 1024 + tid;
        if (f4 < NF4) {
            float4 s4 = reinterpret_cast<const float4*>(scores)[f4];
            #pragma unroll
            for (int q = 0; q < 4; q++) {
                float sc = (q == 0) ? s4.x : (q == 1) ? s4.y : (q == 2) ? s4.z : s4.w;
                if (sc > CTHR) {
                    int i = 4 * f4 + q;
                    int p = atomicAdd(&g_cnt, 1);
                    if (p < CAP) {
                        float px, py, ps;
                        get_prior(i, px, py, ps);
                        float4 l = reinterpret_cast<const float4*>(loc)[i];
                        float4 b = decode_box(l, px, py, ps);
                        g_ckeys[p] = ((unsigned long long)__float_as_uint(sc) << 32)
                                   | (unsigned long long)(0xFFFFFFFFu - (unsigned)i);
                        g_cbox[p] = b;
                        g_carea[p] = box_area(b);
                    }
                }
            }
        }
    }

    // ---------------- grid barrier A (all 66 blocks co-resident: safe) ----------
    __threadfence();
    __syncthreads();
    if (tid == 0) {
        atomicAdd(&g_barA, 1);
        while (atomicAdd(&g_barA, 0) < NB) { }
    }
    __syncthreads();
    __threadfence();            // gpu-scope fence -> CCTL.IVALL (fresh L1 reads)

    int cnt_all = g_cnt;
    int n = cnt_all < CAP ? cnt_all : CAP;

    // ---------------- phase 2: rank (blocks 0-1) || suppress (blocks 2-65) ------
    if (bid < 2) {
        for (int t = tid; t < n; t += 1024) smu.sk[t] = g_ckeys[t];
        __syncthreads();
        int slot = bid * 1024 + tid;
        if (slot < n) {
            unsigned long long k = smu.sk[slot];
            int rank = 0;
            #pragma unroll 8
            for (int j = 0; j < n; j++) rank += (smu.sk[j] > k) ? 1 : 0;
            g_rank[slot] = rank;
            g_slotofrank[rank] = slot;
        }
        __syncthreads();        // sk reuse safety before block 0 reaches resolve
    } else {
        int t = (bid - 2) * 1024 + tid;        // [0, 65536)
        int i = t & (CAP - 1);
        int w = t >> 11;                       // 0..31
        int jbase = w * 64;
        if (i < n && jbase + 63 > i) {
            float4 bi = g_cbox[i];
            float ai = g_carea[i];
            unsigned long long ki = g_ckeys[i];
            int j0 = (i + 1 > jbase) ? i + 1 : jbase;
            int j1 = (jbase + 64 < n) ? jbase + 64 : n;
            for (int j = j0; j < j1; j++) {
                if (iou_gt(bi, ai, g_cbox[j], g_carea[j])) {
                    unsigned long long kj = g_ckeys[j];
                    int supd = (ki > kj) ? j : i;        // smaller key suppressed
                    int supr = (ki > kj) ? i : j;
                    int slot = atomicAdd(&g_supcnt[supd], 1);
                    if (slot < SUPK) g_suplist[supd * SUPK + slot] = supr;
                }
            }
        }
    }

    // ---------------- grid barrier B (non-zero blocks arrive and exit) ----------
    __threadfence();
    __syncthreads();
    if (tid == 0) atomicAdd(&g_barB, 1);
    if (bid != 0) return;
    if (tid == 0) {
        while (atomicAdd(&g_barB, 0) < NB) { }
    }
    __syncthreads();
    __threadfence();

    // ---------------- phase 3: resolve + finalize (block 0 only) ----------------
    RV* sm = &smu.rv;
    int j1 = tid, j2 = tid + 1024;              // slot ids

    int c1 = (j1 < n) ? g_supcnt[j1] : 0;
    int c2 = (j2 < n) ? g_supcnt[j2] : 0;
    sm->s_cnt[j1] = c1;
    sm->s_cnt[j2] = c2;
    bool a1 = (j1 < n) && (c1 > 0);
    bool a2 = (j2 < n) && (c2 > 0);
    sm->s_kept[j1] = ((j1 < n) && c1 == 0) ? 1 : 0;
    sm->s_kept[j2] = ((j2 < n) && c2 == 0) ? 1 : 0;
    int ovf = __syncthreads_or((c1 > SUPK) || (c2 > SUPK));

    {
        unsigned b1 = __ballot_sync(FULLM, a1);
        unsigned b2 = __ballot_sync(FULLM, a2);
        if (lane == 0) { sm->s_ab[wi] = b1; sm->s_ab[32 + wi] = b2; }
    }
    __syncthreads();
    if (tid < 32) {
        int cA = __popc(sm->s_ab[tid]);
        int cB = __popc(sm->s_ab[tid + 32]);
        int sA = cA, sB = cB;
        #pragma unroll
        for (int o = 1; o < 32; o <<= 1) { int v = __shfl_up_sync(FULLM, sA, o); if (lane >= o) sA += v; }
        int totA = __shfl_sync(FULLM, sA, 31);
        #pragma unroll
        for (int o = 1; o < 32; o <<= 1) { int v = __shfl_up_sync(FULLM, sB, o); if (lane >= o) sB += v; }
        int totB = __shfl_sync(FULLM, sB, 31);
        sm->s_awbase[tid] = sA - cA;
        sm->s_awbase[tid + 32] = totA + sB - cB;
        if (tid == 0) sm->s_namb = totA + totB;
    }
    __syncthreads();
    int namb = sm->s_namb;

    if (a1) { int r = sm->s_awbase[wi] + __popc(sm->s_ab[wi] & lt); if (r < AMB_MAX) sm->s_alist[r] = j1; }
    if (a2) { int r = sm->s_awbase[32 + wi] + __popc(sm->s_ab[32 + wi] & lt); if (r < AMB_MAX) sm->s_alist[r] = j2; }
    __syncthreads();

    if (namb <= AMB_MAX) {
        if (tid < namb) sm->s_arank[tid] = g_rank[sm->s_alist[tid]];
        __syncthreads();
        if (tid < namb) {
            int myr = sm->s_arank[tid];
            int pos = 0;
            for (int b = 0; b < namb; b++) pos += (sm->s_arank[b] < myr) ? 1 : 0;
            sm->s_alist2[pos] = sm->s_alist[tid];
        }
        __syncthreads();
        for (int idx = tid; idx < namb * 32; idx += 1024) {
            int a = idx >> 5, l = idx & 31;
            int slot = sm->s_alist2[a];
            int c = sm->s_cnt[slot]; if (c > SUPK) c = SUPK;
            if (l < c) sm->s_asup[idx] = g_suplist[slot * SUPK + l];
        }
        __syncthreads();
        if (tid == 0) {
            for (int a = 0; a < namb; a++) {
                int slot = sm->s_alist2[a];
                int c = sm->s_cnt[slot]; if (c > SUPK) c = SUPK;
                int k = 1;
                for (int l = 0; l < c; l++)
                    if (sm->s_kept[sm->s_asup[a * 32 + l]]) { k = 0; break; }
                sm->s_kept[slot] = (unsigned char)k;
            }
        }
        __syncthreads();
    }

    // ---- kept flags by RANK; ranks via ballot prefix-scan ----
    int r1 = tid, r2 = tid + 1024;
    int slot1 = (r1 < n) ? g_slotofrank[r1] : 0;
    int slot2 = (r2 < n) ? g_slotofrank[r2] : 0;
    bool k1 = (r1 < n) && (sm->s_kept[slot1] != 0);
    bool k2 = (r2 < n) && (sm->s_kept[slot2] != 0);
    {
        unsigned b1 = __ballot_sync(FULLM, k1);
        unsigned b2 = __ballot_sync(FULLM, k2);
        if (lane == 0) { sm->s_kb[wi] = b1; sm->s_kb[32 + wi] = b2; }
    }
    __syncthreads();
    if (tid < 32) {
        int cA = __popc(sm->s_kb[tid]);
        int cB = __popc(sm->s_kb[tid + 32]);
        int sA = cA, sB = cB;
        #pragma unroll
        for (int o = 1; o < 32; o <<= 1) { int v = __shfl_up_sync(FULLM, sA, o); if (lane >= o) sA += v; }
        int totA = __shfl_sync(FULLM, sA, 31);
        #pragma unroll
        for (int o = 1; o < 32; o <<= 1) { int v = __shfl_up_sync(FULLM, sB, o); if (lane >= o) sB += v; }
        int totB = __shfl_sync(FULLM, sB, 31);
        sm->s_wbase[tid] = sA - cA;
        sm->s_wbase[tid + 32] = totA + sB - cB;
        if (tid == 0) sm->s_ktot = totA + totB;
    }
    __syncthreads();
    int ktot = sm->s_ktot;

    bool fb = ovf || (cnt_all > CAP) || (namb > AMB_MAX) || (ktot < MAXK);

    float thr = thrp[0];
    float* ob = out;                 // [750,4]
    float* os = out + MAXK * 4;      // [750]
    float* ol = out + MAXK * 5;      // [750,10]

    if (!fb) {
        // ---- FAST finalize: ktot >= 750 -> every out row written exactly once ----
        #pragma unroll
        for (int h = 0; h < 2; h++) {
            int r = (h == 0) ? r1 : r2;
            bool kp = (h == 0) ? k1 : k2;
            int slot = (h == 0) ? slot1 : slot2;
            if (kp) {
                int w = r >> 5;
                int pos = sm->s_wbase[w] + __popc(sm->s_kb[w] & lt);
                if (pos < MAXK) {
                    unsigned long long key = g_ckeys[slot];
                    int orig = (int)(0xFFFFFFFFu - (unsigned)(key & 0xFFFFFFFFull));
                    float sc = __uint_as_float((unsigned)(key >> 32));
                    if (sc > thr) {
                        float4 b = g_cbox[slot];
                        ob[4 * pos + 0] = b.x; ob[4 * pos + 1] = b.y;
                        ob[4 * pos + 2] = b.z; ob[4 * pos + 3] = b.w;
                        os[pos] = sc;
                        float px, py, ps;
                        get_prior(orig, px, py, ps);
                        #pragma unroll
                        for (int q = 0; q < 5; q++) {
                            float ox = landms[10 * orig + 2 * q + 0];
                            float oy = landms[10 * orig + 2 * q + 1];
                            ol[10 * pos + 2 * q + 0] = __fmul_rn(__fadd_rn(px, __fmul_rn(__fmul_rn(ox, 0.1f), ps)), 2560.0f);
                            ol[10 * pos + 2 * q + 1] = __fmul_rn(__fadd_rn(py, __fmul_rn(__fmul_rn(oy, 0.1f), ps)), 2560.0f);
                        }
                    } else {
                        ob[4 * pos + 0] = 0.f; ob[4 * pos + 1] = 0.f;
                        ob[4 * pos + 2] = 0.f; ob[4 * pos + 3] = 0.f;
                        os[pos] = 0.f;
                        #pragma unroll
                        for (int q = 0; q < 10; q++) ol[10 * pos + q] = 0.f;
                    }
                }
            }
        }
    } else {
        // ---- guaranteed-correct full reference fallback (never expected) ----
        for (int i = tid; i < N_PRIORS; i += 1024) {
            float px, py, ps;
            get_prior(i, px, py, ps);
            float4 l = reinterpret_cast<const float4*>(loc)[i];
            g_boxes[i] = decode_box(l, px, py, ps);
        }
        for (int w = tid; w < NSUPW; w += 1024) g_supp[w] = 0u;
        __syncthreads();

        int kept = 0;
        for (int it = 0; it < MAXK; it++) {
            float bs = -1.0f; int bi = 0x7FFFFFFF;
            for (int i = tid; i < N_PRIORS; i += 1024) {
                if (!((g_supp[i >> 5] >> (i & 31)) & 1u)) {
                    float s = scores[i];
                    if (s > bs || (s == bs && i < bi)) { bs = s; bi = i; }
                }
            }
            sm->rs_[tid] = bs; sm->ri_[tid] = bi;
            __syncthreads();
            for (int off = 512; off > 0; off >>= 1) {
                if (tid < off) {
                    float so = sm->rs_[tid + off]; int io = sm->ri_[tid + off];
                    if (so > sm->rs_[tid] || (so == sm->rs_[tid] && io < sm->ri_[tid])) {
                        sm->rs_[tid] = so; sm->ri_[tid] = io;
                    }
                }
                __syncthreads();
            }
            float topS = sm->rs_[0]; int top = sm->ri_[0];
            __syncthreads();
            if (topS < 0.0f) break;

            if (tid == 0) sm->s_keep_orig[kept] = top;
            kept++;

            float4 bt = g_boxes[top];
            float at = box_area(bt);
            for (int i = tid; i < N_PRIORS; i += 1024) {
                float4 bx = g_boxes[i];
                if (iou_gt(bt, at, bx, box_area(bx)))
                    atomicOr(&g_supp[i >> 5], 1u << (i & 31));
            }
            __syncthreads();
        }
        if (tid == 0) sm->s_fkept = kept;
        __syncthreads();
        int fkept = sm->s_fkept;

        if (tid < MAXK) {
            int i = tid;
            float4 b = make_float4(0.f, 0.f, 0.f, 0.f);
            float s = 0.f;
            float lm[10];
            #pragma unroll
            for (int q = 0; q < 10; q++) lm[q] = 0.f;

            if (i < fkept) {
                int orig = sm->s_keep_orig[i];
                float sc = scores[orig];
                if (sc > thr) {
                    b = g_boxes[orig];
                    s = sc;
                    float px, py, ps;
                    get_prior(orig, px, py, ps);
                    #pragma unroll
                    for (int q = 0; q < 5; q++) {
                        float ox = landms[10 * orig + 2 * q + 0];
                        float oy = landms[10 * orig + 2 * q + 1];
                        lm[2 * q + 0] = __fmul_rn(__fadd_rn(px, __fmul_rn(__fmul_rn(ox, 0.1f), ps)), 2560.0f);
                        lm[2 * q + 1] = __fmul_rn(__fadd_rn(py, __fmul_rn(__fmul_rn(oy, 0.1f), ps)), 2560.0f);
                    }
                }
            }
            ob[4 * i + 0] = b.x; ob[4 * i + 1] = b.y;
            ob[4 * i + 2] = b.z; ob[4 * i + 3] = b.w;
            os[i] = s;
            #pragma unroll
            for (int q = 0; q < 10; q++) ol[10 * i + q] = lm[q];
        }
    }

    // ---- tail reset for next graph replay (block 0; all others exited) ----
    __syncthreads();
    g_supcnt[j1] = 0;
    g_supcnt[j2] = 0;
    if (tid == 0) { g_cnt = 0; g_barA = 0; g_barB = 0; }
}

// ---------------- launch ----------------
extern "C" void kernel_launch(void* const* d_in, const int* in_sizes, int n_in,
                              void* d_out, int out_size) {
    const float* bboxes = (const float*)d_in[0];   // (1, N, 4)
    const float* scores = (const float*)d_in[1];   // (1, N)
    const float* landms = (const float*)d_in[2];   // (1, N, 10)
    const float* thr    = (const float*)d_in[3];   // (1,)
    float* out = (float*)d_out;
    cudaStream_t stream = 0;

    fused_kernel<<<NB, 1024, 0, stream>>>(bboxes, scores, landms, thr, out);
}